// round 14
// baseline (speedup 1.0000x reference)
#include <cuda_runtime.h>

#define EPSK 1e-7f

typedef unsigned long long u64;

constexpr int Bn = 2, Hh = 192, Ww = 192, HQ = 384;

// ---- packed f32x2 helpers (sm_103a) ---------------------------------------
__device__ __forceinline__ u64 pack2(float lo, float hi) {
    u64 r; asm("mov.b64 %0,{%1,%2};" : "=l"(r) : "f"(lo), "f"(hi)); return r;
}
__device__ __forceinline__ void unpack2(float& lo, float& hi, u64 v) {
    asm("mov.b64 {%0,%1},%2;" : "=f"(lo), "=f"(hi) : "l"(v));
}
__device__ __forceinline__ void fma2(u64& d, u64 a, u64 b) {
    asm("fma.rn.f32x2 %0,%1,%2,%0;" : "+l"(d) : "l"(a), "l"(b));
}

// Scratch (no allocations allowed -> __device__ globals)
__device__ float g_a4[Bn * 96 * 96 * 32];
__device__ float g_a32[Bn * 24 * 24 * 32];
__device__ float g_X[Bn * Hh * Ww * 96];     // concat a2 | up(a4) | up(a32)
__device__ float g_aspp[Bn * Hh * Ww * 96];  // conv3x3 output
__device__ float g_P[Bn * Hh * Ww * 64];     // aspp @ mw0[:96] + mb0

// ---------------------------------------------------------------------------
// Fused 1x1 conv + ReLU, f32x2: 2 pixels per warp, float4 input loads.
// ---------------------------------------------------------------------------
__global__ void __launch_bounds__(256)
conv1x1_fused(const float* __restrict__ f2, const float* __restrict__ f4,
              const float* __restrict__ f32v,
              const float* __restrict__ w2, const float* __restrict__ b2,
              const float* __restrict__ w4, const float* __restrict__ b4,
              const float* __restrict__ w32, const float* __restrict__ b32,
              float* __restrict__ X, float* __restrict__ a4, float* __restrict__ a32)
{
    __shared__ float ws[160 * 32];
    int bid = blockIdx.x;
    const float *in, *w, *bia;
    float* out;
    int Cin, outStride, pbase;
    if (bid < 4608)      { in = f2;  w = w2;  bia = b2;  out = X;   Cin = 64;  outStride = 96; pbase = bid * 16; }
    else if (bid < 5760) { in = f4;  w = w4;  bia = b4;  out = a4;  Cin = 96;  outStride = 32; pbase = (bid - 4608) * 16; }
    else                 { in = f32v; w = w32; bia = b32; out = a32; Cin = 160; outStride = 32; pbase = (bid - 5760) * 16; }

    int tid = threadIdx.x;
    for (int i = tid; i < Cin * 32; i += 256) ws[i] = w[i];
    __syncthreads();
    int warp = tid >> 5, lane = tid & 31;
    int ocp = lane & 15;
    int px = lane >> 4;
    int p = pbase + warp * 2 + px;
    const float4* ip4 = (const float4*)(in + (size_t)p * Cin);
    u64 acc = pack2(bia[2 * ocp], bia[2 * ocp + 1]);
    int n4 = Cin >> 2;
#pragma unroll 4
    for (int k4 = 0; k4 < n4; k4++) {
        float4 x = ip4[k4];
        const float* wk = ws + (k4 * 4) * 32 + 2 * ocp;
        fma2(acc, pack2(x.x, x.x), *(const u64*)(wk));
        fma2(acc, pack2(x.y, x.y), *(const u64*)(wk + 32));
        fma2(acc, pack2(x.z, x.z), *(const u64*)(wk + 64));
        fma2(acc, pack2(x.w, x.w), *(const u64*)(wk + 96));
    }
    float a0, a1;
    unpack2(a0, a1, acc);
    float2 r = make_float2(fmaxf(a0, 0.0f), fmaxf(a1, 0.0f));
    *(float2*)(out + (size_t)p * outStride + 2 * ocp) = r;
}

// ---------------------------------------------------------------------------
// Fused bilinear upsample of both 32-ch maps into concat channels 32..95.
// ---------------------------------------------------------------------------
__global__ void __launch_bounds__(256)
upsample_fused(const float* __restrict__ a4, const float* __restrict__ a32,
               float* __restrict__ X)
{
    int bid = blockIdx.x;
    const float* in;
    int inH, inW, chOff;
    if (bid < 2304) { in = a4; inH = 96; inW = 96; chOff = 32; }
    else            { in = a32; inH = 24; inW = 24; chOff = 64; bid -= 2304; }

    int idx = bid * 256 + threadIdx.x;
    int c4 = idx & 7;
    int pix = idx >> 3;
    int x = pix % Ww;
    int t = pix / Ww;
    int y = t % Hh;
    int b = t / Hh;

    float sy = (y + 0.5f) * (float)inH / (float)Hh - 0.5f;
    float sx = (x + 0.5f) * (float)inW / (float)Ww - 0.5f;
    float fy0 = floorf(sy), fx0 = floorf(sx);
    float fy = sy - fy0, fx = sx - fx0;
    int y0 = (int)fy0, x0 = (int)fx0;
    int y1 = min(y0 + 1, inH - 1), x1 = min(x0 + 1, inW - 1);
    y0 = max(y0, 0);
    x0 = max(x0, 0);

    const float4* ip = (const float4*)in;
    float4 v00 = ip[(((size_t)b * inH + y0) * inW + x0) * 8 + c4];
    float4 v01 = ip[(((size_t)b * inH + y0) * inW + x1) * 8 + c4];
    float4 v10 = ip[(((size_t)b * inH + y1) * inW + x0) * 8 + c4];
    float4 v11 = ip[(((size_t)b * inH + y1) * inW + x1) * 8 + c4];
    float w00 = (1.f - fy) * (1.f - fx), w01 = (1.f - fy) * fx;
    float w10 = fy * (1.f - fx), w11 = fy * fx;
    float4 r;
    r.x = v00.x * w00 + v01.x * w01 + v10.x * w10 + v11.x * w11;
    r.y = v00.y * w00 + v01.y * w01 + v10.y * w10 + v11.y * w11;
    r.z = v00.z * w00 + v01.z * w01 + v10.z * w10 + v11.z * w11;
    r.w = v00.w * w00 + v01.w * w01 + v10.w * w10 + v11.w * w11;
    *(float4*)(X + (((size_t)b * Hh + y) * Ww + x) * 96 + chOff + c4 * 4) = r;
}

// ---------------------------------------------------------------------------
// 3x3 conv (zero pad SAME) 96->96 + bias + ReLU (R8/R11-proven config).
// ---------------------------------------------------------------------------
__global__ void __launch_bounds__(256)
conv3x3_kernel(const float* __restrict__ X, const float* __restrict__ wf,
               const float* __restrict__ bf, float* __restrict__ out)
{
    __shared__ u64 in_s[16 * 218];     // [ic][ry*12 + rx] packed (v,v)
    __shared__ float ws[9 * 16 * 32];  // [kk][ic][oc]
    int tx0 = blockIdx.x * 8, ty0 = blockIdx.y * 16;
    int b = blockIdx.z / 3, ocg = blockIdx.z % 3;
    int tid = threadIdx.x;
    int ocp = tid & 15;
    int row = tid >> 4;   // 0..15

    u64 acc[8];
#pragma unroll
    for (int i = 0; i < 8; i++) acc[i] = 0ull;

#pragma unroll 1
    for (int icc = 0; icc < 6; icc++) {
        int icb = icc * 16;
        __syncthreads();
        for (int i = tid; i < 2880; i += 256) {
            int ic = i & 15;
            int rp = i >> 4;
            int rx = rp % 10, ry = rp / 10;
            int gy = ty0 + ry - 1, gx = tx0 + rx - 1;
            float v = 0.0f;
            if ((unsigned)gy < (unsigned)Hh && (unsigned)gx < (unsigned)Ww)
                v = X[(((size_t)b * Hh + gy) * Ww + gx) * 96 + icb + ic];
            in_s[ic * 218 + ry * 12 + rx] = pack2(v, v);
        }
        for (int i = tid; i < 4608; i += 256) {
            int o = i & 31;
            int r = i >> 5;
            int ic = r & 15;
            int kk = r >> 4;
            ws[i] = wf[((size_t)kk * 96 + icb + ic) * 96 + ocg * 32 + o];
        }
        __syncthreads();
#pragma unroll
        for (int dy = 0; dy < 3; dy++) {
#pragma unroll
            for (int ic = 0; ic < 16; ic++) {
                const ulonglong2* xrow =
                    (const ulonglong2*)(in_s + ic * 218 + (row + dy) * 12);
                u64 xp[10];
#pragma unroll
                for (int t = 0; t < 5; t++) {
                    ulonglong2 v = xrow[t];
                    xp[2 * t] = v.x;
                    xp[2 * t + 1] = v.y;
                }
#pragma unroll
                for (int dx = 0; dx < 3; dx++) {
                    u64 wv = *(const u64*)(ws + ((dy * 3 + dx) * 16 + ic) * 32 + 2 * ocp);
#pragma unroll
                    for (int col = 0; col < 8; col++) fma2(acc[col], xp[col + dx], wv);
                }
            }
        }
    }
    float bb0 = bf[ocg * 32 + 2 * ocp];
    float bb1 = bf[ocg * 32 + 2 * ocp + 1];
#pragma unroll
    for (int col = 0; col < 8; col++) {
        int gy = ty0 + row, gx = tx0 + col;
        float a, c;
        unpack2(a, c, acc[col]);
        float2 r;
        r.x = fmaxf(a + bb0, 0.0f);
        r.y = fmaxf(c + bb1, 0.0f);
        *(float2*)(out + (((size_t)b * Hh + gy) * Ww + gx) * 96 + ocg * 32 + 2 * ocp) = r;
    }
}

// ---------------------------------------------------------------------------
// Per-pixel MLP-layer-1 feature projection: P = aspp @ mw0[0:96] + mb0.
// ---------------------------------------------------------------------------
__global__ void __launch_bounds__(256)
proj_kernel(const float* __restrict__ aspp, const float* __restrict__ mw0,
            const float* __restrict__ mb0, float* __restrict__ P)
{
    __shared__ float ws[96 * 64];
    int tid = threadIdx.x;
    for (int i = tid; i < 96 * 64; i += 256) ws[i] = mw0[i];
    __syncthreads();
    int warp = tid >> 5, lane = tid & 31;
    int pbase = blockIdx.x * 32 + warp * 4;
    const float4* ip0 = (const float4*)(aspp + (size_t)(pbase + 0) * 96);
    const float4* ip1 = (const float4*)(aspp + (size_t)(pbase + 1) * 96);
    const float4* ip2 = (const float4*)(aspp + (size_t)(pbase + 2) * 96);
    const float4* ip3 = (const float4*)(aspp + (size_t)(pbase + 3) * 96);
    float b0 = mb0[2 * lane], b1 = mb0[2 * lane + 1];
    float a0l = b0, a0h = b1, a1l = b0, a1h = b1;
    float a2l = b0, a2h = b1, a3l = b0, a3h = b1;
#pragma unroll 2
    for (int k4 = 0; k4 < 24; k4++) {
        float4 x0 = ip0[k4], x1 = ip1[k4], x2 = ip2[k4], x3 = ip3[k4];
        const float* wk = ws + (k4 * 4) * 64 + 2 * lane;
#pragma unroll
        for (int c = 0; c < 4; c++) {
            float2 w = *(const float2*)(wk + c * 64);
            float xc0 = (c == 0) ? x0.x : (c == 1) ? x0.y : (c == 2) ? x0.z : x0.w;
            float xc1 = (c == 0) ? x1.x : (c == 1) ? x1.y : (c == 2) ? x1.z : x1.w;
            float xc2 = (c == 0) ? x2.x : (c == 1) ? x2.y : (c == 2) ? x2.z : x2.w;
            float xc3 = (c == 0) ? x3.x : (c == 1) ? x3.y : (c == 2) ? x3.z : x3.w;
            a0l += xc0 * w.x; a0h += xc0 * w.y;
            a1l += xc1 * w.x; a1h += xc1 * w.y;
            a2l += xc2 * w.x; a2h += xc2 * w.y;
            a3l += xc3 * w.x; a3h += xc3 * w.y;
        }
    }
    *(float2*)(P + (size_t)(pbase + 0) * 64 + 2 * lane) = make_float2(a0l, a0h);
    *(float2*)(P + (size_t)(pbase + 1) * 64 + 2 * lane) = make_float2(a1l, a1h);
    *(float2*)(P + (size_t)(pbase + 2) * 64 + 2 * lane) = make_float2(a2l, a2h);
    *(float2*)(P + (size_t)(pbase + 3) * 64 + 2 * lane) = make_float2(a3l, a3h);
}

// ---------------------------------------------------------------------------
// Decode: 2 threads per query (adjacent lanes), each owning one vy corner
// pair; half-width output passes keep live regs ~130 -> (128,3) = 12
// warps/SM (decode was latency-bound at 8 warps/SM, fma floor 160us).
// Final blend combined via shfl_xor(1). Per-element fma order unchanged.
// ---------------------------------------------------------------------------
__global__ void __launch_bounds__(128, 3)
decode_kernel(const float* __restrict__ P, const float* __restrict__ coords,
              const float* __restrict__ cells, const float* __restrict__ mw0,
              const float* __restrict__ mw1, const float* __restrict__ mb1,
              const float* __restrict__ mw2, const float* __restrict__ mb2,
              float* __restrict__ out)
{
    __shared__ __align__(16) float sw1[64 * 64];
    __shared__ __align__(16) u64 sw0t[32 * 8];
    __shared__ __align__(16) float sb1[64];
    __shared__ float sw2[64];
    __shared__ float sb2s;
    int tid = threadIdx.x;
    for (int i = tid; i < 64 * 64; i += 128) sw1[i] = mw1[i];
    for (int i = tid; i < 32 * 8; i += 128) {
        int kp = i >> 3, e = i & 7;
        u64 v = 0ull;
        if (e < 6) {
            const float* src = mw0 + 96 * 64 + e * 64 + 2 * kp;
            v = pack2(src[0], src[1]);
        }
        sw0t[i] = v;
    }
    if (tid < 64) { sb1[tid] = mb1[tid]; sw2[tid] = mw2[tid]; }
    if (tid == 0) sb2s = mb2[0];
    __syncthreads();

    int q = blockIdx.x * 64 + (tid >> 1);  // 294912 = 4608 * 64 exact
    int pairSel = tid & 1;                 // 0: vy=-1 (corners 0,1), 1: vy=+1
    int b = q / (HQ * HQ);
    float cy = coords[2 * q], cx = coords[2 * q + 1];
    float clh = cells[2 * q] * (float)Hh, clw = cells[2 * q + 1] * (float)Ww;
    const float rr = 1.0f / (float)Hh;

    float vyA = pairSel ? 1.0f : -1.0f;
    float relyA, relxA, relxB;
    const float4 *prowA4, *prowB4;
    {
        float ccy = fminf(fmaxf(cy + vyA * rr + EPSK, -1.0f + EPSK), 1.0f - EPSK);
        int iy = (int)rintf((ccy + 1.0f) * (float)Hh / 2.0f - 0.5f);
        iy = min(max(iy, 0), Hh - 1);
        float sampy = ((iy + 0.5f) / (float)Hh) * 2.0f - 1.0f;
        float ccxA = fminf(fmaxf(cx - rr + EPSK, -1.0f + EPSK), 1.0f - EPSK);
        float ccxB = fminf(fmaxf(cx + rr + EPSK, -1.0f + EPSK), 1.0f - EPSK);
        int ixA = (int)rintf((ccxA + 1.0f) * (float)Ww / 2.0f - 0.5f);
        int ixB = (int)rintf((ccxB + 1.0f) * (float)Ww / 2.0f - 0.5f);
        ixA = min(max(ixA, 0), Ww - 1);
        ixB = min(max(ixB, 0), Ww - 1);
        float sampxA = ((ixA + 0.5f) / (float)Ww) * 2.0f - 1.0f;
        float sampxB = ((ixB + 0.5f) / (float)Ww) * 2.0f - 1.0f;
        relyA = (cy - sampy) * (float)Hh;
        relxA = (cx - sampxA) * (float)Ww;
        relxB = (cx - sampxB) * (float)Ww;
        prowA4 = (const float4*)(P + (((size_t)b * Hh + iy) * Ww + ixA) * 64);
        prowB4 = (const float4*)(P + (((size_t)b * Hh + iy) * Ww + ixB) * 64);
    }
    u64 xry = pack2(relyA, relyA);
    u64 xrxA = pack2(relxA, relxA), xrxB = pack2(relxB, relxB);
    u64 xcy = pack2(cy, cy), xcx = pack2(cx, cx);
    u64 xch = pack2(clh, clh), xcw = pack2(clw, clw);

    float prA = sb2s, prB = sb2s;
#pragma unroll 1
    for (int half = 0; half < 2; half++) {
        u64 h1a[16], h1b[16];
        const ulonglong2* bp = (const ulonglong2*)(sb1 + half * 32);
#pragma unroll
        for (int j = 0; j < 8; j++) {
            ulonglong2 v = bp[j];
            h1a[2 * j] = v.x; h1a[2 * j + 1] = v.y;
            h1b[2 * j] = v.x; h1b[2 * j + 1] = v.y;
        }
#pragma unroll 1
        for (int k4 = 0; k4 < 16; k4++) {
            float4 rA = prowA4[k4];
            float4 rB = prowB4[k4];
#pragma unroll
            for (int sub = 0; sub < 2; sub++) {
                int kp = 2 * k4 + sub;
                u64 pvA = sub ? pack2(rA.z, rA.w) : pack2(rA.x, rA.y);
                u64 pvB = sub ? pack2(rB.z, rB.w) : pack2(rB.x, rB.y);
                const ulonglong2* wt = (const ulonglong2*)(sw0t + kp * 8);
                ulonglong2 w01 = wt[0], w23 = wt[1], w45 = wt[2];
                fma2(pvA, xry, w01.x);  fma2(pvB, xry, w01.x);
                fma2(pvA, xrxA, w01.y); fma2(pvB, xrxB, w01.y);
                fma2(pvA, xcy, w23.x);  fma2(pvB, xcy, w23.x);
                fma2(pvA, xcx, w23.y);  fma2(pvB, xcx, w23.y);
                fma2(pvA, xch, w45.x);  fma2(pvB, xch, w45.x);
                fma2(pvA, xcw, w45.y);  fma2(pvB, xcw, w45.y);
                float loA, hiA, loB, hiB;
                unpack2(loA, hiA, pvA);
                unpack2(loB, hiB, pvB);
                u64 xa0 = pack2(fmaxf(loA, 0.0f), fmaxf(loA, 0.0f));
                u64 xa1 = pack2(fmaxf(hiA, 0.0f), fmaxf(hiA, 0.0f));
                u64 xb0 = pack2(fmaxf(loB, 0.0f), fmaxf(loB, 0.0f));
                u64 xb1 = pack2(fmaxf(hiB, 0.0f), fmaxf(hiB, 0.0f));
                const ulonglong2* wr0 =
                    (const ulonglong2*)(sw1 + (2 * kp) * 64 + half * 32);
                const ulonglong2* wr1 =
                    (const ulonglong2*)(sw1 + (2 * kp + 1) * 64 + half * 32);
#pragma unroll
                for (int j = 0; j < 8; j++) {
                    ulonglong2 w = wr0[j];
                    fma2(h1a[2 * j], xa0, w.x);
                    fma2(h1a[2 * j + 1], xa0, w.y);
                    fma2(h1b[2 * j], xb0, w.x);
                    fma2(h1b[2 * j + 1], xb0, w.y);
                }
#pragma unroll
                for (int j = 0; j < 8; j++) {
                    ulonglong2 w = wr1[j];
                    fma2(h1a[2 * j], xa1, w.x);
                    fma2(h1a[2 * j + 1], xa1, w.y);
                    fma2(h1b[2 * j], xb1, w.x);
                    fma2(h1b[2 * j + 1], xb1, w.y);
                }
            }
        }
#pragma unroll
        for (int j = 0; j < 16; j++) {
            float2 w2v = *(const float2*)(sw2 + half * 32 + 2 * j);
            float a, c;
            unpack2(a, c, h1a[j]);
            prA += fmaxf(a, 0.0f) * w2v.x + fmaxf(c, 0.0f) * w2v.y;
            unpack2(a, c, h1b[j]);
            prB += fmaxf(a, 0.0f) * w2v.x + fmaxf(c, 0.0f) * w2v.y;
        }
    }
    float arA = fabsf(relyA * relxA) + EPSK;
    float arB = fabsf(relyA * relxB) + EPSK;

    // exchange with the partner thread (other vy pair): lane ^ 1
    float o_prA = __shfl_xor_sync(0xffffffffu, prA, 1);
    float o_prB = __shfl_xor_sync(0xffffffffu, prB, 1);
    float o_arA = __shfl_xor_sync(0xffffffffu, arA, 1);
    float o_arB = __shfl_xor_sync(0xffffffffu, arB, 1);
    if (pairSel == 0) {
        // self = corners 0 (A), 1 (B); partner = corners 2 (A), 3 (B)
        // num = p0*ar3 + p1*ar2 + p2*ar1 + p3*ar0
        float num = prA * o_arB + prB * o_arA + o_prA * arB + o_prB * arA;
        float den = arA + arB + o_arA + o_arB;
        out[q] = num / den;
    }
}

// ---------------------------------------------------------------------------
extern "C" void kernel_launch(void* const* d_in, const int* in_sizes, int n_in,
                              void* d_out, int out_size)
{
    const float* feats2  = (const float*)d_in[0];
    const float* feats4  = (const float*)d_in[1];
    const float* feats32 = (const float*)d_in[2];
    const float* coords  = (const float*)d_in[3];
    const float* cells   = (const float*)d_in[4];
    const float* w2  = (const float*)d_in[5];
    const float* b2  = (const float*)d_in[6];
    const float* w4  = (const float*)d_in[7];
    const float* b4  = (const float*)d_in[8];
    const float* w32 = (const float*)d_in[9];
    const float* b32 = (const float*)d_in[10];
    const float* wf  = (const float*)d_in[11];
    const float* bf  = (const float*)d_in[12];
    const float* mw0 = (const float*)d_in[13];
    const float* mb0 = (const float*)d_in[14];
    const float* mw1 = (const float*)d_in[15];
    const float* mb1 = (const float*)d_in[16];
    const float* mw2 = (const float*)d_in[17];
    const float* mb2 = (const float*)d_in[18];
    float* out = (float*)d_out;

    float *a4p, *a32p, *Xp, *asppp, *Pp;
    cudaGetSymbolAddress((void**)&a4p, g_a4);
    cudaGetSymbolAddress((void**)&a32p, g_a32);
    cudaGetSymbolAddress((void**)&Xp, g_X);
    cudaGetSymbolAddress((void**)&asppp, g_aspp);
    cudaGetSymbolAddress((void**)&Pp, g_P);

    // 1) all three 1x1 convs (f32x2, 2 px/warp, float4 input loads)
    conv1x1_fused<<<5832, 256>>>(feats2, feats4, feats32, w2, b2, w4, b4,
                                 w32, b32, Xp, a4p, a32p);
    // 2) both bilinear upsamples -> X ch32..95
    upsample_fused<<<4608, 256>>>(a4p, a32p, Xp);
    // 3) 3x3 conv + ReLU (R8 16x8 tile, 256 threads)
    dim3 g3(24, 12, 6);
    conv3x3_kernel<<<g3, 256>>>(Xp, wf, bf, asppp);
    // 4) per-pixel projection (4 px/warp weight reuse)
    proj_kernel<<<2304, 256>>>(asppp, mw0, mb0, Pp);
    // 5) decode: 2 threads/query, half-width passes, (128,3) occupancy
    decode_kernel<<<4608, 128>>>(Pp, coords, cells, mw0, mw1, mb1, mw2, mb2, out);
}

// round 17
// speedup vs baseline: 1.0278x; 1.0278x over previous
#include <cuda_runtime.h>

#define EPSK 1e-7f

typedef unsigned long long u64;

constexpr int Bn = 2, Hh = 192, Ww = 192, HQ = 384;

// ---- packed f32x2 helpers (sm_103a) ---------------------------------------
__device__ __forceinline__ u64 pack2(float lo, float hi) {
    u64 r; asm("mov.b64 %0,{%1,%2};" : "=l"(r) : "f"(lo), "f"(hi)); return r;
}
__device__ __forceinline__ void unpack2(float& lo, float& hi, u64 v) {
    asm("mov.b64 {%0,%1},%2;" : "=f"(lo), "=f"(hi) : "l"(v));
}
__device__ __forceinline__ void fma2(u64& d, u64 a, u64 b) {
    asm("fma.rn.f32x2 %0,%1,%2,%0;" : "+l"(d) : "l"(a), "l"(b));
}

// Scratch (no allocations allowed -> __device__ globals)
__device__ float g_a4[Bn * 96 * 96 * 32];
__device__ float g_a32[Bn * 24 * 24 * 32];
__device__ float g_X[Bn * Hh * Ww * 96];     // concat a2 | up(a4) | up(a32)
__device__ float g_aspp[Bn * Hh * Ww * 96];  // conv3x3 output
__device__ float g_P[Bn * Hh * Ww * 64];     // aspp @ mw0[:96] + mb0

// ---------------------------------------------------------------------------
// Fused 1x1 conv + ReLU, f32x2: 2 pixels per warp, float4 input loads.
// ---------------------------------------------------------------------------
__global__ void __launch_bounds__(256)
conv1x1_fused(const float* __restrict__ f2, const float* __restrict__ f4,
              const float* __restrict__ f32v,
              const float* __restrict__ w2, const float* __restrict__ b2,
              const float* __restrict__ w4, const float* __restrict__ b4,
              const float* __restrict__ w32, const float* __restrict__ b32,
              float* __restrict__ X, float* __restrict__ a4, float* __restrict__ a32)
{
    __shared__ float ws[160 * 32];
    int bid = blockIdx.x;
    const float *in, *w, *bia;
    float* out;
    int Cin, outStride, pbase;
    if (bid < 4608)      { in = f2;  w = w2;  bia = b2;  out = X;   Cin = 64;  outStride = 96; pbase = bid * 16; }
    else if (bid < 5760) { in = f4;  w = w4;  bia = b4;  out = a4;  Cin = 96;  outStride = 32; pbase = (bid - 4608) * 16; }
    else                 { in = f32v; w = w32; bia = b32; out = a32; Cin = 160; outStride = 32; pbase = (bid - 5760) * 16; }

    int tid = threadIdx.x;
    for (int i = tid; i < Cin * 32; i += 256) ws[i] = w[i];
    __syncthreads();
    int warp = tid >> 5, lane = tid & 31;
    int ocp = lane & 15;
    int px = lane >> 4;
    int p = pbase + warp * 2 + px;
    const float4* ip4 = (const float4*)(in + (size_t)p * Cin);
    u64 acc = pack2(bia[2 * ocp], bia[2 * ocp + 1]);
    int n4 = Cin >> 2;
#pragma unroll 4
    for (int k4 = 0; k4 < n4; k4++) {
        float4 x = ip4[k4];
        const float* wk = ws + (k4 * 4) * 32 + 2 * ocp;
        fma2(acc, pack2(x.x, x.x), *(const u64*)(wk));
        fma2(acc, pack2(x.y, x.y), *(const u64*)(wk + 32));
        fma2(acc, pack2(x.z, x.z), *(const u64*)(wk + 64));
        fma2(acc, pack2(x.w, x.w), *(const u64*)(wk + 96));
    }
    float a0, a1;
    unpack2(a0, a1, acc);
    float2 r = make_float2(fmaxf(a0, 0.0f), fmaxf(a1, 0.0f));
    *(float2*)(out + (size_t)p * outStride + 2 * ocp) = r;
}

// ---------------------------------------------------------------------------
// Fused bilinear upsample of both 32-ch maps into concat channels 32..95.
// ---------------------------------------------------------------------------
__global__ void __launch_bounds__(256)
upsample_fused(const float* __restrict__ a4, const float* __restrict__ a32,
               float* __restrict__ X)
{
    int bid = blockIdx.x;
    const float* in;
    int inH, inW, chOff;
    if (bid < 2304) { in = a4; inH = 96; inW = 96; chOff = 32; }
    else            { in = a32; inH = 24; inW = 24; chOff = 64; bid -= 2304; }

    int idx = bid * 256 + threadIdx.x;
    int c4 = idx & 7;
    int pix = idx >> 3;
    int x = pix % Ww;
    int t = pix / Ww;
    int y = t % Hh;
    int b = t / Hh;

    float sy = (y + 0.5f) * (float)inH / (float)Hh - 0.5f;
    float sx = (x + 0.5f) * (float)inW / (float)Ww - 0.5f;
    float fy0 = floorf(sy), fx0 = floorf(sx);
    float fy = sy - fy0, fx = sx - fx0;
    int y0 = (int)fy0, x0 = (int)fx0;
    int y1 = min(y0 + 1, inH - 1), x1 = min(x0 + 1, inW - 1);
    y0 = max(y0, 0);
    x0 = max(x0, 0);

    const float4* ip = (const float4*)in;
    float4 v00 = ip[(((size_t)b * inH + y0) * inW + x0) * 8 + c4];
    float4 v01 = ip[(((size_t)b * inH + y0) * inW + x1) * 8 + c4];
    float4 v10 = ip[(((size_t)b * inH + y1) * inW + x0) * 8 + c4];
    float4 v11 = ip[(((size_t)b * inH + y1) * inW + x1) * 8 + c4];
    float w00 = (1.f - fy) * (1.f - fx), w01 = (1.f - fy) * fx;
    float w10 = fy * (1.f - fx), w11 = fy * fx;
    float4 r;
    r.x = v00.x * w00 + v01.x * w01 + v10.x * w10 + v11.x * w11;
    r.y = v00.y * w00 + v01.y * w01 + v10.y * w10 + v11.y * w11;
    r.z = v00.z * w00 + v01.z * w01 + v10.z * w10 + v11.z * w11;
    r.w = v00.w * w00 + v01.w * w01 + v10.w * w10 + v11.w * w11;
    *(float4*)(X + (((size_t)b * Hh + y) * Ww + x) * 96 + chOff + c4 * 4) = r;
}

// ---------------------------------------------------------------------------
// 3x3 conv (zero pad SAME) 96->96 + bias + ReLU.
// 256 threads = 8 ocq (4 oc each) x 2 colhalf (4 cols) x 16 rows.
// Per (dy,ic): 3 x-LDS.128 + 3 w-LDS.128 + 24 fma2 (was 5+3+24).
// Same tile (16x8x32oc), same occupancy, identical accumulation order.
// ---------------------------------------------------------------------------
__global__ void __launch_bounds__(256)
conv3x3_kernel(const float* __restrict__ X, const float* __restrict__ wf,
               const float* __restrict__ bf, float* __restrict__ out)
{
    __shared__ u64 in_s[16 * 218];     // [ic][ry*12 + rx] packed (v,v)
    __shared__ float ws[9 * 16 * 32];  // [kk][ic][oc]
    int tx0 = blockIdx.x * 8, ty0 = blockIdx.y * 16;
    int b = blockIdx.z / 3, ocg = blockIdx.z % 3;
    int tid = threadIdx.x;
    int ocq = tid & 7;          // 4 oc: 4*ocq .. 4*ocq+3
    int ch = (tid >> 3) & 1;    // col half: cols ch*4 .. ch*4+3
    int row = tid >> 4;         // 0..15

    u64 acc[4][2];
#pragma unroll
    for (int i = 0; i < 4; i++) { acc[i][0] = 0ull; acc[i][1] = 0ull; }

#pragma unroll 1
    for (int icc = 0; icc < 6; icc++) {
        int icb = icc * 16;
        __syncthreads();
        for (int i = tid; i < 2880; i += 256) {
            int ic = i & 15;
            int rp = i >> 4;
            int rx = rp % 10, ry = rp / 10;
            int gy = ty0 + ry - 1, gx = tx0 + rx - 1;
            float v = 0.0f;
            if ((unsigned)gy < (unsigned)Hh && (unsigned)gx < (unsigned)Ww)
                v = X[(((size_t)b * Hh + gy) * Ww + gx) * 96 + icb + ic];
            in_s[ic * 218 + ry * 12 + rx] = pack2(v, v);
        }
        for (int i = tid; i < 4608; i += 256) {
            int o = i & 31;
            int r = i >> 5;
            int ic = r & 15;
            int kk = r >> 4;
            ws[i] = wf[((size_t)kk * 96 + icb + ic) * 96 + ocg * 32 + o];
        }
        __syncthreads();
#pragma unroll
        for (int dy = 0; dy < 3; dy++) {
#pragma unroll
            for (int ic = 0; ic < 16; ic++) {
                const ulonglong2* xrow =
                    (const ulonglong2*)(in_s + ic * 218 + (row + dy) * 12 + ch * 4);
                u64 xp[6];
#pragma unroll
                for (int t = 0; t < 3; t++) {
                    ulonglong2 v = xrow[t];
                    xp[2 * t] = v.x;
                    xp[2 * t + 1] = v.y;
                }
#pragma unroll
                for (int dx = 0; dx < 3; dx++) {
                    ulonglong2 w = *(const ulonglong2*)(
                        ws + ((dy * 3 + dx) * 16 + ic) * 32 + 4 * ocq);
#pragma unroll
                    for (int col = 0; col < 4; col++) {
                        fma2(acc[col][0], xp[col + dx], w.x);
                        fma2(acc[col][1], xp[col + dx], w.y);
                    }
                }
            }
        }
    }
    float4 bb = *(const float4*)(bf + ocg * 32 + 4 * ocq);
#pragma unroll
    for (int col = 0; col < 4; col++) {
        int gy = ty0 + row, gx = tx0 + ch * 4 + col;
        float a0, a1, a2, a3;
        unpack2(a0, a1, acc[col][0]);
        unpack2(a2, a3, acc[col][1]);
        float4 r;
        r.x = fmaxf(a0 + bb.x, 0.0f);
        r.y = fmaxf(a1 + bb.y, 0.0f);
        r.z = fmaxf(a2 + bb.z, 0.0f);
        r.w = fmaxf(a3 + bb.w, 0.0f);
        *(float4*)(out + (((size_t)b * Hh + gy) * Ww + gx) * 96 + ocg * 32 + 4 * ocq) = r;
    }
}

// ---------------------------------------------------------------------------
// Per-pixel MLP-layer-1 feature projection: P = aspp @ mw0[0:96] + mb0.
// ---------------------------------------------------------------------------
__global__ void __launch_bounds__(256)
proj_kernel(const float* __restrict__ aspp, const float* __restrict__ mw0,
            const float* __restrict__ mb0, float* __restrict__ P)
{
    __shared__ float ws[96 * 64];
    int tid = threadIdx.x;
    for (int i = tid; i < 96 * 64; i += 256) ws[i] = mw0[i];
    __syncthreads();
    int warp = tid >> 5, lane = tid & 31;
    int pbase = blockIdx.x * 32 + warp * 4;
    const float4* ip0 = (const float4*)(aspp + (size_t)(pbase + 0) * 96);
    const float4* ip1 = (const float4*)(aspp + (size_t)(pbase + 1) * 96);
    const float4* ip2 = (const float4*)(aspp + (size_t)(pbase + 2) * 96);
    const float4* ip3 = (const float4*)(aspp + (size_t)(pbase + 3) * 96);
    float b0 = mb0[2 * lane], b1 = mb0[2 * lane + 1];
    float a0l = b0, a0h = b1, a1l = b0, a1h = b1;
    float a2l = b0, a2h = b1, a3l = b0, a3h = b1;
#pragma unroll 2
    for (int k4 = 0; k4 < 24; k4++) {
        float4 x0 = ip0[k4], x1 = ip1[k4], x2 = ip2[k4], x3 = ip3[k4];
        const float* wk = ws + (k4 * 4) * 64 + 2 * lane;
#pragma unroll
        for (int c = 0; c < 4; c++) {
            float2 w = *(const float2*)(wk + c * 64);
            float xc0 = (c == 0) ? x0.x : (c == 1) ? x0.y : (c == 2) ? x0.z : x0.w;
            float xc1 = (c == 0) ? x1.x : (c == 1) ? x1.y : (c == 2) ? x1.z : x1.w;
            float xc2 = (c == 0) ? x2.x : (c == 1) ? x2.y : (c == 2) ? x2.z : x2.w;
            float xc3 = (c == 0) ? x3.x : (c == 1) ? x3.y : (c == 2) ? x3.z : x3.w;
            a0l += xc0 * w.x; a0h += xc0 * w.y;
            a1l += xc1 * w.x; a1h += xc1 * w.y;
            a2l += xc2 * w.x; a2h += xc2 * w.y;
            a3l += xc3 * w.x; a3h += xc3 * w.y;
        }
    }
    *(float2*)(P + (size_t)(pbase + 0) * 64 + 2 * lane) = make_float2(a0l, a0h);
    *(float2*)(P + (size_t)(pbase + 1) * 64 + 2 * lane) = make_float2(a1l, a1h);
    *(float2*)(P + (size_t)(pbase + 2) * 64 + 2 * lane) = make_float2(a2l, a2h);
    *(float2*)(P + (size_t)(pbase + 3) * 64 + 2 * lane) = make_float2(a3l, a3h);
}

// ---------------------------------------------------------------------------
// Decode (R13-proven): ALL 4 corners share every weight load; sw1 read once
// per query per half. (128,2) register envelope.
// ---------------------------------------------------------------------------
__global__ void __launch_bounds__(128, 2)
decode_kernel(const float* __restrict__ P, const float* __restrict__ coords,
              const float* __restrict__ cells, const float* __restrict__ mw0,
              const float* __restrict__ mw1, const float* __restrict__ mb1,
              const float* __restrict__ mw2, const float* __restrict__ mb2,
              float* __restrict__ out)
{
    __shared__ __align__(16) float sw1[64 * 64];
    __shared__ __align__(16) u64 sw0t[32 * 8];
    __shared__ __align__(16) float sb1[64];
    __shared__ float sw2[64];
    __shared__ float sb2s;
    int tid = threadIdx.x;
    for (int i = tid; i < 64 * 64; i += 128) sw1[i] = mw1[i];
    for (int i = tid; i < 32 * 8; i += 128) {
        int kp = i >> 3, e = i & 7;
        u64 v = 0ull;
        if (e < 6) {
            const float* src = mw0 + 96 * 64 + e * 64 + 2 * kp;
            v = pack2(src[0], src[1]);
        }
        sw0t[i] = v;
    }
    if (tid < 64) { sb1[tid] = mb1[tid]; sw2[tid] = mw2[tid]; }
    if (tid == 0) sb2s = mb2[0];
    __syncthreads();

    int q = blockIdx.x * 128 + tid;  // 294912 = 2304 * 128 exact
    int b = q / (HQ * HQ);
    float cy = coords[2 * q], cx = coords[2 * q + 1];
    float clh = cells[2 * q] * (float)Hh, clw = cells[2 * q + 1] * (float)Ww;
    const float rr = 1.0f / (float)Hh;

    float relyv[2], relxv[2];
    int iyv[2], ixv[2];
#pragma unroll
    for (int s = 0; s < 2; s++) {
        float v = s ? 1.0f : -1.0f;
        float ccy = fminf(fmaxf(cy + v * rr + EPSK, -1.0f + EPSK), 1.0f - EPSK);
        int iy = (int)rintf((ccy + 1.0f) * (float)Hh / 2.0f - 0.5f);
        iy = min(max(iy, 0), Hh - 1);
        relyv[s] = (cy - (((iy + 0.5f) / (float)Hh) * 2.0f - 1.0f)) * (float)Hh;
        iyv[s] = iy;
        float ccx = fminf(fmaxf(cx + v * rr + EPSK, -1.0f + EPSK), 1.0f - EPSK);
        int ix = (int)rintf((ccx + 1.0f) * (float)Ww / 2.0f - 0.5f);
        ix = min(max(ix, 0), Ww - 1);
        relxv[s] = (cx - (((ix + 0.5f) / (float)Ww) * 2.0f - 1.0f)) * (float)Ww;
        ixv[s] = ix;
    }
    const float4* prow[4];
    prow[0] = (const float4*)(P + (((size_t)b * Hh + iyv[0]) * Ww + ixv[0]) * 64);
    prow[1] = (const float4*)(P + (((size_t)b * Hh + iyv[0]) * Ww + ixv[1]) * 64);
    prow[2] = (const float4*)(P + (((size_t)b * Hh + iyv[1]) * Ww + ixv[0]) * 64);
    prow[3] = (const float4*)(P + (((size_t)b * Hh + iyv[1]) * Ww + ixv[1]) * 64);

    u64 xry0 = pack2(relyv[0], relyv[0]), xry1 = pack2(relyv[1], relyv[1]);
    u64 xrx0 = pack2(relxv[0], relxv[0]), xrx1 = pack2(relxv[1], relxv[1]);
    u64 xcy = pack2(cy, cy), xcx = pack2(cx, cx);
    u64 xch = pack2(clh, clh), xcw = pack2(clw, clw);

    float pr[4];
#pragma unroll
    for (int c = 0; c < 4; c++) pr[c] = sb2s;

#pragma unroll 1
    for (int half = 0; half < 2; half++) {
        u64 h1[4][16];
        const ulonglong2* bp = (const ulonglong2*)(sb1 + half * 32);
#pragma unroll
        for (int j = 0; j < 8; j++) {
            ulonglong2 v = bp[j];
#pragma unroll
            for (int c = 0; c < 4; c++) {
                h1[c][2 * j] = v.x;
                h1[c][2 * j + 1] = v.y;
            }
        }

#pragma unroll 1
        for (int k4 = 0; k4 < 16; k4++) {
            float4 r0 = prow[0][k4];
            float4 r1 = prow[1][k4];
            float4 r2 = prow[2][k4];
            float4 r3 = prow[3][k4];
#pragma unroll
            for (int sub = 0; sub < 2; sub++) {
                int kp = 2 * k4 + sub;
                u64 pv[4];
                pv[0] = sub ? pack2(r0.z, r0.w) : pack2(r0.x, r0.y);
                pv[1] = sub ? pack2(r1.z, r1.w) : pack2(r1.x, r1.y);
                pv[2] = sub ? pack2(r2.z, r2.w) : pack2(r2.x, r2.y);
                pv[3] = sub ? pack2(r3.z, r3.w) : pack2(r3.x, r3.y);
                const ulonglong2* wt = (const ulonglong2*)(sw0t + kp * 8);
                ulonglong2 w01 = wt[0], w23 = wt[1], w45 = wt[2];
                fma2(pv[0], xry0, w01.x); fma2(pv[1], xry0, w01.x);
                fma2(pv[2], xry1, w01.x); fma2(pv[3], xry1, w01.x);
                fma2(pv[0], xrx0, w01.y); fma2(pv[1], xrx1, w01.y);
                fma2(pv[2], xrx0, w01.y); fma2(pv[3], xrx1, w01.y);
#pragma unroll
                for (int c = 0; c < 4; c++) {
                    fma2(pv[c], xcy, w23.x);
                    fma2(pv[c], xcx, w23.y);
                    fma2(pv[c], xch, w45.x);
                    fma2(pv[c], xcw, w45.y);
                }
                u64 xlo[4], xhi[4];
#pragma unroll
                for (int c = 0; c < 4; c++) {
                    float lo, hi;
                    unpack2(lo, hi, pv[c]);
                    float rl = fmaxf(lo, 0.0f), rh = fmaxf(hi, 0.0f);
                    xlo[c] = pack2(rl, rl);
                    xhi[c] = pack2(rh, rh);
                }
                const ulonglong2* wr0 =
                    (const ulonglong2*)(sw1 + (2 * kp) * 64 + half * 32);
                const ulonglong2* wr1 =
                    (const ulonglong2*)(sw1 + (2 * kp + 1) * 64 + half * 32);
#pragma unroll
                for (int j = 0; j < 8; j++) {
                    ulonglong2 w = wr0[j];
#pragma unroll
                    for (int c = 0; c < 4; c++) {
                        fma2(h1[c][2 * j], xlo[c], w.x);
                        fma2(h1[c][2 * j + 1], xlo[c], w.y);
                    }
                }
#pragma unroll
                for (int j = 0; j < 8; j++) {
                    ulonglong2 w = wr1[j];
#pragma unroll
                    for (int c = 0; c < 4; c++) {
                        fma2(h1[c][2 * j], xhi[c], w.x);
                        fma2(h1[c][2 * j + 1], xhi[c], w.y);
                    }
                }
            }
        }

#pragma unroll
        for (int j = 0; j < 16; j++) {
            float2 w2v = *(const float2*)(sw2 + half * 32 + 2 * j);
#pragma unroll
            for (int c = 0; c < 4; c++) {
                float a, d;
                unpack2(a, d, h1[c][j]);
                pr[c] += fmaxf(a, 0.0f) * w2v.x + fmaxf(d, 0.0f) * w2v.y;
            }
        }
    }

    float ar0 = fabsf(relyv[0] * relxv[0]) + EPSK;
    float ar1 = fabsf(relyv[0] * relxv[1]) + EPSK;
    float ar2 = fabsf(relyv[1] * relxv[0]) + EPSK;
    float ar3 = fabsf(relyv[1] * relxv[1]) + EPSK;
    float num = pr[0] * ar3 + pr[1] * ar2 + pr[2] * ar1 + pr[3] * ar0;
    float den = ar0 + ar1 + ar2 + ar3;
    out[q] = num / den;
}

// ---------------------------------------------------------------------------
extern "C" void kernel_launch(void* const* d_in, const int* in_sizes, int n_in,
                              void* d_out, int out_size)
{
    const float* feats2  = (const float*)d_in[0];
    const float* feats4  = (const float*)d_in[1];
    const float* feats32 = (const float*)d_in[2];
    const float* coords  = (const float*)d_in[3];
    const float* cells   = (const float*)d_in[4];
    const float* w2  = (const float*)d_in[5];
    const float* b2  = (const float*)d_in[6];
    const float* w4  = (const float*)d_in[7];
    const float* b4  = (const float*)d_in[8];
    const float* w32 = (const float*)d_in[9];
    const float* b32 = (const float*)d_in[10];
    const float* wf  = (const float*)d_in[11];
    const float* bf  = (const float*)d_in[12];
    const float* mw0 = (const float*)d_in[13];
    const float* mb0 = (const float*)d_in[14];
    const float* mw1 = (const float*)d_in[15];
    const float* mb1 = (const float*)d_in[16];
    const float* mw2 = (const float*)d_in[17];
    const float* mb2 = (const float*)d_in[18];
    float* out = (float*)d_out;

    float *a4p, *a32p, *Xp, *asppp, *Pp;
    cudaGetSymbolAddress((void**)&a4p, g_a4);
    cudaGetSymbolAddress((void**)&a32p, g_a32);
    cudaGetSymbolAddress((void**)&Xp, g_X);
    cudaGetSymbolAddress((void**)&asppp, g_aspp);
    cudaGetSymbolAddress((void**)&Pp, g_P);

    // 1) all three 1x1 convs (f32x2, 2 px/warp, float4 input loads)
    conv1x1_fused<<<5832, 256>>>(feats2, feats4, feats32, w2, b2, w4, b4,
                                 w32, b32, Xp, a4p, a32p);
    // 2) both bilinear upsamples -> X ch32..95
    upsample_fused<<<4608, 256>>>(a4p, a32p, Xp);
    // 3) 3x3 conv + ReLU (16x8 tile, 256 thr, 4-oc/4-col threads)
    dim3 g3(24, 12, 6);
    conv3x3_kernel<<<g3, 256>>>(Xp, wf, bf, asppp);
    // 4) per-pixel projection (4 px/warp weight reuse)
    proj_kernel<<<2304, 256>>>(asppp, mw0, mb0, Pp);
    // 5) per-query decode: all 4 corners share every weight load (R13)
    decode_kernel<<<2304, 128>>>(Pp, coords, cells, mw0, mw1, mb1, mw2, mb2, out);
}